// round 6
// baseline (speedup 1.0000x reference)
#include <cuda_runtime.h>

#define E_DIM 8
#define F_DIM 32
#define TPT 2          // tokens per thread
#define THREADS 256
#define F_CONST 24     // w2 rows [0,24) from constant; [24,32) from smem

using u64 = unsigned long long;

// Layer-1 weights + most of layer-2 weights on the constant port.
__constant__ __align__(16) float c_w1[E_DIM * F_DIM];    // [E][F] row-major, 1KB
__constant__ __align__(16) float c_w2p[F_CONST * E_DIM]; // w2 rows 0..23, 768B

__device__ __forceinline__ u64 pack2(float lo, float hi) {
    u64 r;
    asm("mov.b64 %0, {%1, %2};" : "=l"(r) : "f"(lo), "f"(hi));
    return r;
}
__device__ __forceinline__ void unpack2(u64 v, float& lo, float& hi) {
    asm("mov.b64 {%0, %1}, %2;" : "=f"(lo), "=f"(hi) : "l"(v));
}
// Packed dual fp32 FMA (Blackwell f32x2 pipe).
__device__ __forceinline__ u64 fma2(u64 a, u64 b, u64 c) {
    u64 d;
    asm("fma.rn.f32x2 %0, %1, %2, %3;" : "=l"(d) : "l"(a), "l"(b), "l"(c));
    return d;
}

__global__ void __launch_bounds__(THREADS, 4)
ffq_kernel(const float* __restrict__ x,
           const float* __restrict__ w2,    // [F][E]; rows 24..31 used here
           const float* __restrict__ b1,
           const float* __restrict__ b2,
           const float* __restrict__ theta,
           float* __restrict__ out,
           long long n_tokens)
{
    // smem side of the port split: w2 tail rows + biases + theta.
    __shared__ __align__(16) u64 sw2t[(F_DIM - F_CONST) * (E_DIM / 2)]; // 32 u64
    __shared__ __align__(16) u64 sb1[F_DIM / 2];                        // 16 u64
    __shared__ __align__(16) u64 sb2[E_DIM / 2];                        // 4 u64
    __shared__ float sth[E_DIM];

    const int t = threadIdx.x;
    if (t < 32)       sw2t[t]      = ((const u64*)w2)[96 + t]; // rows 24..31
    else if (t < 48)  sb1[t - 32]  = ((const u64*)b1)[t - 32];
    else if (t < 52)  sb2[t - 48]  = ((const u64*)b2)[t - 48];
    else if (t < 60)  sth[t - 52]  = theta[t - 52];
    __syncthreads();

    const long long token0 =
        ((long long)blockIdx.x * THREADS + t) * TPT;
    if (token0 + 1 >= n_tokens) return;

    // ---- load x for 2 tokens: 64 contiguous bytes ----
    const float4* xp = (const float4*)(x + token0 * E_DIM);
    float4 a0 = xp[0], a1 = xp[1], a2 = xp[2], a3 = xp[3];

    // ---- quantum layer: q = cos(x + theta), pre-packed (q,q) ----
    u64 q0[E_DIM], q1[E_DIM];
    {
        float c;
        c = __cosf(a0.x + sth[0]); q0[0] = pack2(c, c);
        c = __cosf(a0.y + sth[1]); q0[1] = pack2(c, c);
        c = __cosf(a0.z + sth[2]); q0[2] = pack2(c, c);
        c = __cosf(a0.w + sth[3]); q0[3] = pack2(c, c);
        c = __cosf(a1.x + sth[4]); q0[4] = pack2(c, c);
        c = __cosf(a1.y + sth[5]); q0[5] = pack2(c, c);
        c = __cosf(a1.z + sth[6]); q0[6] = pack2(c, c);
        c = __cosf(a1.w + sth[7]); q0[7] = pack2(c, c);
        c = __cosf(a2.x + sth[0]); q1[0] = pack2(c, c);
        c = __cosf(a2.y + sth[1]); q1[1] = pack2(c, c);
        c = __cosf(a2.z + sth[2]); q1[2] = pack2(c, c);
        c = __cosf(a2.w + sth[3]); q1[3] = pack2(c, c);
        c = __cosf(a3.x + sth[4]); q1[4] = pack2(c, c);
        c = __cosf(a3.y + sth[5]); q1[5] = pack2(c, c);
        c = __cosf(a3.z + sth[6]); q1[6] = pack2(c, c);
        c = __cosf(a3.w + sth[7]); q1[7] = pack2(c, c);
    }

    // ---- output accumulators: packed E pairs, init with b2 (smem) ----
    u64 o0[E_DIM / 2], o1[E_DIM / 2];
    o0[0] = sb2[0]; o0[1] = sb2[1]; o0[2] = sb2[2]; o0[3] = sb2[3];
    o1[0] = o0[0];  o1[1] = o0[1];  o1[2] = o0[2];  o1[3] = o0[3];

    // ---- fused layer1+layer2, 4 F-columns per iteration ----
#pragma unroll
    for (int f4 = 0; f4 < F_DIM / 4; f4++) {
        // layer 1: h for 4 f-values; b1 pairs come straight from smem
        ulonglong2 bp = *(const ulonglong2*)&sb1[f4 * 2];   // LDS.128
        u64 hA0 = bp.x, hB0 = bp.y;
        u64 hA1 = hA0,  hB1 = hB0;
#pragma unroll
        for (int i = 0; i < E_DIM; i++) {
            float4 w = *(const float4*)&c_w1[i * F_DIM + f4 * 4];  // LDC.128
            u64 wA = pack2(w.x, w.y), wB = pack2(w.z, w.w);
            hA0 = fma2(q0[i], wA, hA0);
            hB0 = fma2(q0[i], wB, hB0);
            hA1 = fma2(q1[i], wA, hA1);
            hB1 = fma2(q1[i], wB, hB1);
        }

        // relu + layer 2 for these 4 f-values
        float h0[4], h1[4];
        unpack2(hA0, h0[0], h0[1]); unpack2(hB0, h0[2], h0[3]);
        unpack2(hA1, h1[0], h1[1]); unpack2(hB1, h1[2], h1[3]);
#pragma unroll
        for (int j = 0; j < 4; j++) {
            const int f = f4 * 4 + j;
            float d0 = fmaxf(h0[j], 0.0f);
            float d1 = fmaxf(h1[j], 0.0f);
            u64 p0 = pack2(d0, d0), p1 = pack2(d1, d1);

            u64 w01, w23, w45, w67;
            if (f < F_CONST) {
                float4 wa = *(const float4*)&c_w2p[f * E_DIM];      // LDC.128
                float4 wb = *(const float4*)&c_w2p[f * E_DIM + 4];  // LDC.128
                w01 = pack2(wa.x, wa.y); w23 = pack2(wa.z, wa.w);
                w45 = pack2(wb.x, wb.y); w67 = pack2(wb.z, wb.w);
            } else {
                ulonglong2 wa = *(const ulonglong2*)&sw2t[(f - F_CONST) * 4];     // LDS.128
                ulonglong2 wb = *(const ulonglong2*)&sw2t[(f - F_CONST) * 4 + 2]; // LDS.128
                w01 = wa.x; w23 = wa.y; w45 = wb.x; w67 = wb.y;
            }
            o0[0] = fma2(p0, w01, o0[0]);
            o0[1] = fma2(p0, w23, o0[1]);
            o0[2] = fma2(p0, w45, o0[2]);
            o0[3] = fma2(p0, w67, o0[3]);
            o1[0] = fma2(p1, w01, o1[0]);
            o1[1] = fma2(p1, w23, o1[1]);
            o1[2] = fma2(p1, w45, o1[2]);
            o1[3] = fma2(p1, w67, o1[3]);
        }
    }

    // ---- store 2 tokens: 64 contiguous bytes ----
    float4 r0, r1, r2, r3;
    unpack2(o0[0], r0.x, r0.y); unpack2(o0[1], r0.z, r0.w);
    unpack2(o0[2], r1.x, r1.y); unpack2(o0[3], r1.z, r1.w);
    unpack2(o1[0], r2.x, r2.y); unpack2(o1[1], r2.z, r2.w);
    unpack2(o1[2], r3.x, r3.y); unpack2(o1[3], r3.z, r3.w);
    float4* op = (float4*)(out + token0 * E_DIM);
    op[0] = r0; op[1] = r1; op[2] = r2; op[3] = r3;
}

extern "C" void kernel_launch(void* const* d_in, const int* in_sizes, int n_in,
                              void* d_out, int out_size) {
    const float* x     = (const float*)d_in[0];
    const float* theta = (const float*)d_in[1];
    const float* w1    = (const float*)d_in[2];
    const float* b1    = (const float*)d_in[3];
    const float* w2    = (const float*)d_in[4];
    const float* b2    = (const float*)d_in[5];
    float* out         = (float*)d_out;

    // Only TWO graph memcpy nodes (contiguous prefixes of d_in buffers).
    cudaMemcpyToSymbolAsync(c_w1, w1, E_DIM * F_DIM * sizeof(float), 0,
                            cudaMemcpyDeviceToDevice, 0);
    cudaMemcpyToSymbolAsync(c_w2p, w2, F_CONST * E_DIM * sizeof(float), 0,
                            cudaMemcpyDeviceToDevice, 0);

    const long long n_tokens = (long long)in_sizes[0] / E_DIM;  // B*S
    const long long pairs    = n_tokens / TPT;
    const int blocks         = (int)((pairs + THREADS - 1) / THREADS);

    ffq_kernel<<<blocks, THREADS>>>(x, w2, b1, b2, theta, out, n_tokens);
}